// round 5
// baseline (speedup 1.0000x reference)
#include <cuda_runtime.h>
#include <cuda_bf16.h>
#include <math.h>

// Problem constants
#define Bq   4
#define Tq   2048
#define Cq   1024
#define NH   16
#define HD   64
#define C3   (3 * Cq)          // 3072
#define MQ   (Bq * Tq)         // 8192 rows

// ---------------------------------------------------------------------------
// Scratch (device globals; no runtime allocation allowed)
// ---------------------------------------------------------------------------
__device__ float g_qkv[(size_t)MQ * C3];   // [B*T, 3C]  ~100.7 MB
__device__ float g_y  [(size_t)MQ * Cq];   // [B*T, C]   ~33.6 MB (attn out, [B,T,C] layout)

// ---------------------------------------------------------------------------
// SGEMM: C = A[M,K] @ B[K,N] + bias[N]   (row-major, M,N,K multiples of 128/16)
// 128x128 block tile, 16 K-tile, 256 threads, 8x8 per-thread micro-tile.
// ---------------------------------------------------------------------------
#define BM 128
#define BN 128
#define BK 16
#define TM 8
#define TN 8

__global__ __launch_bounds__(256, 2)
void sgemm_bias_kernel(const float* __restrict__ A, const float* __restrict__ B,
                       const float* __restrict__ bias, float* __restrict__ C,
                       int M, int N, int K)
{
    __shared__ float As[BK][BM];   // A transposed: As[k][m]
    __shared__ float Bs[BK][BN];   // B natural:    Bs[k][n]

    const int tid = threadIdx.x;
    const int tx  = tid & 15;      // 0..15 (n direction)
    const int ty  = tid >> 4;      // 0..15 (m direction)
    const int m0  = blockIdx.y * BM;
    const int n0  = blockIdx.x * BN;

    float acc[TM][TN];
#pragma unroll
    for (int i = 0; i < TM; i++)
#pragma unroll
        for (int j = 0; j < TN; j++) acc[i][j] = 0.0f;

    for (int k0 = 0; k0 < K; k0 += BK) {
        // Load A tile (BM x BK) -> transposed into As
#pragma unroll
        for (int p = 0; p < 2; p++) {
            int linear = tid * 4 + p * 1024;           // 2048 floats total
            int row = linear / BK;                     // 0..127
            int col = linear % BK;                     // multiple of 4
            float4 v = *(const float4*)&A[(size_t)(m0 + row) * K + (k0 + col)];
            As[col + 0][row] = v.x;
            As[col + 1][row] = v.y;
            As[col + 2][row] = v.z;
            As[col + 3][row] = v.w;
        }
        // Load B tile (BK x BN)
#pragma unroll
        for (int p = 0; p < 2; p++) {
            int linear = tid * 4 + p * 1024;
            int row = linear / BN;                     // 0..15
            int col = linear % BN;
            *(float4*)&Bs[row][col] =
                *(const float4*)&B[(size_t)(k0 + row) * N + (n0 + col)];
        }
        __syncthreads();

#pragma unroll
        for (int k = 0; k < BK; k++) {
            float a[TM], b[TN];
            *(float4*)&a[0] = *(const float4*)&As[k][ty * TM];
            *(float4*)&a[4] = *(const float4*)&As[k][ty * TM + 4];
            *(float4*)&b[0] = *(const float4*)&Bs[k][tx * TN];
            *(float4*)&b[4] = *(const float4*)&Bs[k][tx * TN + 4];
#pragma unroll
            for (int i = 0; i < TM; i++)
#pragma unroll
                for (int j = 0; j < TN; j++)
                    acc[i][j] = fmaf(a[i], b[j], acc[i][j]);
        }
        __syncthreads();
    }

    // Epilogue with fused bias
#pragma unroll
    for (int i = 0; i < TM; i++) {
        size_t m = (size_t)(m0 + ty * TM + i);
#pragma unroll
        for (int j = 0; j < TN; j += 4) {
            int n = n0 + tx * TN + j;
            float4 bv = *(const float4*)&bias[n];
            float4 o;
            o.x = acc[i][j + 0] + bv.x;
            o.y = acc[i][j + 1] + bv.y;
            o.z = acc[i][j + 2] + bv.z;
            o.w = acc[i][j + 3] + bv.w;
            *(float4*)&C[m * N + n] = o;
        }
    }
}

// ---------------------------------------------------------------------------
// Flash-attention (fp32, causal) over qkv scratch.
//  grid  = (T/64, B*NH); block = 256 threads (16x16)
//  Each block: 64 queries x full head. K/V streamed in 64-key tiles,
//  online softmax, P written to SMEM (aliasing the K buffer) for the PV GEMM.
//  Output written directly in [B,T,C] layout (merges the head transpose).
// ---------------------------------------------------------------------------

// Swizzled transposed-tile index: element (d, q) of a 64x64 tile stored as
// [d][q] with the 4-aligned q-group XOR-permuted by (d>>2). Keeps float4
// reads contiguous; makes transpose writes conflict-free.
__device__ __forceinline__ int tswz(int d, int q)
{
    return d * 64 + ((((q >> 2) ^ ((d >> 2) & 15)) << 2) | (q & 3));
}

__global__ __launch_bounds__(256, 2)
void attn_kernel(const float* __restrict__ qkv, float* __restrict__ y)
{
    __shared__ float Qt[64 * 64];  // Q transposed/swizzled: (d, q)
    __shared__ float KP[64 * 64];  // K transposed/swizzled (d, kc); then P (k, q)
    __shared__ float Vs[64 * 64];  // V natural: Vs[k*64 + c]

    const int tid = threadIdx.x;
    const int tx  = tid & 15;                 // key / output-col direction
    const int ty  = tid >> 4;                 // query-row direction
    const int bh  = blockIdx.y;
    const int b   = bh >> 4;
    const int h   = bh & 15;
    const int qt  = blockIdx.x;
    const int q0  = qt * 64;
    const float scale = 0.125f;               // 1/sqrt(64)

    const float* qbase = qkv + (size_t)b * Tq * C3 + h * HD;          // Q slice
    const float* kbase = qbase + Cq;                                   // K slice
    const float* vbase = qbase + 2 * Cq;                               // V slice

    // Load Q tile (64 q x 64 d), transposed+swizzled
#pragma unroll
    for (int p = 0; p < 4; p++) {
        int linear = tid * 4 + p * 1024;
        int q = linear / 64;
        int d = linear % 64;                  // multiple of 4
        float4 v = *(const float4*)&qbase[(size_t)(q0 + q) * C3 + d];
        Qt[tswz(d + 0, q)] = v.x;
        Qt[tswz(d + 1, q)] = v.y;
        Qt[tswz(d + 2, q)] = v.z;
        Qt[tswz(d + 3, q)] = v.w;
    }

    float m[4], l[4], acc[4][4];
#pragma unroll
    for (int r = 0; r < 4; r++) {
        m[r] = -1e30f;
        l[r] = 0.0f;
#pragma unroll
        for (int j = 0; j < 4; j++) acc[r][j] = 0.0f;
    }

    for (int kt = 0; kt <= qt; kt++) {
        const int k0 = kt * 64;
        __syncthreads();   // prior PV reads of KP/Vs done (and Qt writes, iter 0)

        // Load K (transposed+swizzled) and V (natural) tiles
#pragma unroll
        for (int p = 0; p < 4; p++) {
            int linear = tid * 4 + p * 1024;
            int kk = linear / 64;
            int d  = linear % 64;
            float4 kv = *(const float4*)&kbase[(size_t)(k0 + kk) * C3 + d];
            KP[tswz(d + 0, kk)] = kv.x;
            KP[tswz(d + 1, kk)] = kv.y;
            KP[tswz(d + 2, kk)] = kv.z;
            KP[tswz(d + 3, kk)] = kv.w;
            float4 vv = *(const float4*)&vbase[(size_t)(k0 + kk) * C3 + d];
            *(float4*)&Vs[kk * 64 + d] = vv;
        }
        __syncthreads();

        // S = Q K^T (thread owns q rows 4ty+r, key cols 4tx+j)
        float s[4][4];
#pragma unroll
        for (int r = 0; r < 4; r++)
#pragma unroll
            for (int j = 0; j < 4; j++) s[r][j] = 0.0f;

#pragma unroll 8
        for (int d = 0; d < 64; d++) {
            float4 qa = *(const float4*)&Qt[tswz(d, 4 * ty)];
            float4 kb = *(const float4*)&KP[tswz(d, 4 * tx)];
            float av[4] = {qa.x, qa.y, qa.z, qa.w};
            float bv[4] = {kb.x, kb.y, kb.z, kb.w};
#pragma unroll
            for (int r = 0; r < 4; r++)
#pragma unroll
                for (int j = 0; j < 4; j++)
                    s[r][j] = fmaf(av[r], bv[j], s[r][j]);
        }

        // Scale + causal mask (only needed on the diagonal tile)
#pragma unroll
        for (int r = 0; r < 4; r++)
#pragma unroll
            for (int j = 0; j < 4; j++) {
                s[r][j] *= scale;
                if (kt == qt && (4 * tx + j) > (4 * ty + r)) s[r][j] = -1e30f;
            }

        // Online softmax; row stats reduced across the 16 same-ty lanes
#pragma unroll
        for (int r = 0; r < 4; r++) {
            float rmax = fmaxf(fmaxf(s[r][0], s[r][1]), fmaxf(s[r][2], s[r][3]));
#pragma unroll
            for (int off = 1; off < 16; off <<= 1)
                rmax = fmaxf(rmax, __shfl_xor_sync(0xffffffffu, rmax, off));
            float mnew  = fmaxf(m[r], rmax);
            float alpha = __expf(m[r] - mnew);
            float rsum  = 0.0f;
#pragma unroll
            for (int j = 0; j < 4; j++) {
                s[r][j] = __expf(s[r][j] - mnew);
                rsum += s[r][j];
            }
#pragma unroll
            for (int off = 1; off < 16; off <<= 1)
                rsum += __shfl_xor_sync(0xffffffffu, rsum, off);
            l[r] = l[r] * alpha + rsum;
            m[r] = mnew;
#pragma unroll
            for (int j = 0; j < 4; j++) acc[r][j] *= alpha;
        }

        __syncthreads();   // everyone finished reading K from KP

        // Write P transposed into KP: Pt(k, q); float4 across the 4 q-rows
#pragma unroll
        for (int j = 0; j < 4; j++) {
            int kk = 4 * tx + j;
            float4 pv = make_float4(s[0][j], s[1][j], s[2][j], s[3][j]);
            *(float4*)&KP[tswz(kk, 4 * ty)] = pv;
        }
        __syncthreads();

        // acc += P @ V  (contract over the 64 keys of this tile)
#pragma unroll 8
        for (int kk = 0; kk < 64; kk++) {
            float4 pp = *(const float4*)&KP[tswz(kk, 4 * ty)];
            float4 vv = *(const float4*)&Vs[kk * 64 + 4 * tx];
            float pv[4] = {pp.x, pp.y, pp.z, pp.w};
            float vw[4] = {vv.x, vv.y, vv.z, vv.w};
#pragma unroll
            for (int r = 0; r < 4; r++)
#pragma unroll
                for (int j = 0; j < 4; j++)
                    acc[r][j] = fmaf(pv[r], vw[j], acc[r][j]);
        }
    }

    // Epilogue: normalize and write to y in [B,T,C] layout (head transpose fused)
#pragma unroll
    for (int r = 0; r < 4; r++) {
        int q = q0 + 4 * ty + r;
        float inv = 1.0f / l[r];
        float4 o = make_float4(acc[r][0] * inv, acc[r][1] * inv,
                               acc[r][2] * inv, acc[r][3] * inv);
        *(float4*)&y[((size_t)b * Tq + q) * Cq + h * HD + 4 * tx] = o;
    }
}

// ---------------------------------------------------------------------------
// Launch
// ---------------------------------------------------------------------------
extern "C" void kernel_launch(void* const* d_in, const int* in_sizes, int n_in,
                              void* d_out, int out_size)
{
    (void)in_sizes; (void)n_in; (void)out_size;
    const float* x      = (const float*)d_in[0];
    const float* W_attn = (const float*)d_in[1];
    const float* b_attn = (const float*)d_in[2];
    const float* W_proj = (const float*)d_in[3];
    const float* b_proj = (const float*)d_in[4];
    float* out = (float*)d_out;

    float *qkv = nullptr, *y = nullptr;
    cudaGetSymbolAddress((void**)&qkv, g_qkv);
    cudaGetSymbolAddress((void**)&y,   g_y);

    dim3 blk(256);
    // 1) qkv = x @ W_attn + b_attn          [8192, 3072]
    sgemm_bias_kernel<<<dim3(C3 / BN, MQ / BM), blk>>>(x, W_attn, b_attn, qkv,
                                                       MQ, C3, Cq);
    // 2) y = causal_attention(qkv)          [B, T, C]
    attn_kernel<<<dim3(Tq / 64, Bq * NH), blk>>>(qkv, y);
    // 3) out = y @ W_proj + b_proj          [8192, 1024]
    sgemm_bias_kernel<<<dim3(Cq / BN, MQ / BM), blk>>>(y, W_proj, b_proj, out,
                                                       MQ, Cq, Cq);
}